// round 15
// baseline (speedup 1.0000x reference)
#include <cuda_runtime.h>
#include <cstdint>

// HONU order-2 as triangular register-blocked GEMM.
//   U[j][n] = W[p(j,n)] (n>=j) else 0;  Y = X U;  out = rowsum(Y .* X) + b
// R15: 2 rows/lane (one x load feeds 4 FMA2 chains per U load -> U traffic
// per row halved, ILP doubled) x 32-way (C,H) split. CTA = 1024 thr =
// 32 warps over a 64-row tile; block A quarter-trip C+1, block B 16-C ->
// 17 balanced iters/warp. 256 CTAs -> 8192 warps. Trips compile-time via
// 8-way C template; H is a runtime base offset (code stays in I$).

#define THREADS 1024
#define XT 66                    // xs_T row stride (floats; even -> 8B align)

__device__ __forceinline__ void fma2(uint64_t& d, uint64_t a, uint64_t b) {
    asm("fma.rn.f32x2 %0, %1, %2, %0;" : "+l"(d) : "l"(a), "l"(b));
}
__device__ __forceinline__ void lds_v2u64(uint64_t& a, uint64_t& b, unsigned addr) {
    asm volatile("ld.shared.v2.b64 {%0,%1}, [%2];" : "=l"(a), "=l"(b) : "r"(addr));
}
__device__ __forceinline__ void lds_v2f32(float& a, float& b, unsigned addr) {
    asm volatile("ld.shared.v2.f32 {%0,%1}, [%2];" : "=f"(a), "=f"(b) : "r"(addr));
}
__device__ __forceinline__ uint64_t splat(float x) {
    uint64_t d;
    asm("mov.b64 %0, {%1,%1};" : "=l"(d) : "r"(__float_as_uint(x)));
    return d;
}
__device__ __forceinline__ float lo32(uint64_t v) {
    uint32_t r; asm("mov.b64 {%0,_}, %1;" : "=r"(r) : "l"(v));
    return __uint_as_float(r);
}
__device__ __forceinline__ float hi32(uint64_t v) {
    uint32_t r; asm("mov.b64 {_,%0}, %1;" : "=r"(r) : "l"(v));
    return __uint_as_float(r);
}

template <int C>
__device__ __forceinline__ void body(unsigned xtb, unsigned ub, int H,
                                     float& p0, float& p1) {
    constexpr int colA = 4 * C;
    constexpr int colB = 60 - 4 * C;
    constexpr int nA   = C + 1;           // quarter-trip, block A
    constexpr int nB   = 16 - C;          // quarter-trip, block B

    uint64_t a0 = 0, a1 = 0, a2 = 0, a3 = 0;   // row0/row1 x colsA {01,23}
    uint64_t b0 = 0, b1 = 0, b2 = 0, b3 = 0;   // row0/row1 x colsB {01,23}

    {   // block A, k = H*nA .. H*nA + nA-1
        const unsigned xA = xtb + (H * nA) * (XT * 4);
        const unsigned uA = ub + (H * nA) * 256 + colA * 4;
        #pragma unroll
        for (int i = 0; i < nA; ++i) {
            float f0, f1;
            lds_v2f32(f0, f1, xA + i * (XT * 4));     // rows 2l, 2l+1: 2 wf
            uint64_t x0 = splat(f0), x1 = splat(f1);
            uint64_t u0, u1;
            lds_v2u64(u0, u1, uA + i * 256);          // uniform 16B
            fma2(a0, u0, x0); fma2(a1, u1, x0);
            fma2(a2, u0, x1); fma2(a3, u1, x1);
        }
    }
    {   // block B, k = H*nB .. H*nB + nB-1
        const unsigned xB = xtb + (H * nB) * (XT * 4);
        const unsigned uB = ub + (H * nB) * 256 + colB * 4;
        #pragma unroll
        for (int i = 0; i < nB; ++i) {
            float f0, f1;
            lds_v2f32(f0, f1, xB + i * (XT * 4));
            uint64_t x0 = splat(f0), x1 = splat(f1);
            uint64_t u0, u1;
            lds_v2u64(u0, u1, uB + i * 256);
            fma2(b0, u0, x0); fma2(b1, u1, x0);
            fma2(b2, u0, x1); fma2(b3, u1, x1);
        }
    }

    // Partial dot with x columns (linear in k -> summable across H)
    float qx[8], qy[8];
    #pragma unroll
    for (int c = 0; c < 4; ++c) {
        lds_v2f32(qx[c],     qy[c],     xtb + (colA + c) * (XT * 4));
        lds_v2f32(qx[4 + c], qy[4 + c], xtb + (colB + c) * (XT * 4));
    }
    p0 = lo32(a0) * qx[0] + hi32(a0) * qx[1] + lo32(a1) * qx[2] + hi32(a1) * qx[3]
       + lo32(b0) * qx[4] + hi32(b0) * qx[5] + lo32(b1) * qx[6] + hi32(b1) * qx[7];
    p1 = lo32(a2) * qy[0] + hi32(a2) * qy[1] + lo32(a3) * qy[2] + hi32(a3) * qy[3]
       + lo32(b2) * qy[4] + hi32(b2) * qy[5] + lo32(b3) * qy[6] + hi32(b3) * qy[7];
}

__global__ void __launch_bounds__(THREADS, 1) honu_kernel(
    const float* __restrict__ x, const float* __restrict__ W,
    const float* __restrict__ bias, float* __restrict__ out)
{
    __shared__ __align__(16) float U_s[64 * 64];     // 16 KB
    __shared__ __align__(8)  float xs_T[64 * XT];    // 16.5 KB transposed
    __shared__ __align__(8)  float part[32][64];     // 8 KB

    const int tid  = threadIdx.x;
    const int wid  = tid >> 5;
    const int lane = tid & 31;
    const int row0 = blockIdx.x * 64;

    // --- Expand U from packed W in-CTA (4 elements/thread; W L2-resident)
    #pragma unroll
    for (int it = 0; it < 4; ++it) {
        int e = it * THREADS + tid;                  // 0..4095
        int j = e >> 6, n = e & 63;
        float v = 0.0f;
        if (n >= j) v = __ldg(&W[j * 64 - ((j * (j - 1)) >> 1) + (n - j)]);
        U_s[e] = v;
    }
    // --- Stage 64x64 x tile transposed: xs_T[k][r] = x[row0+r][k]
    {
        const float4* xg4 = reinterpret_cast<const float4*>(x + (size_t)row0 * 64);
        int r = tid >> 4, c4 = tid & 15;             // 1024 float4s, 1/thread
        float4 v = xg4[tid];
        xs_T[(4 * c4 + 0) * XT + r] = v.x;
        xs_T[(4 * c4 + 1) * XT + r] = v.y;
        xs_T[(4 * c4 + 2) * XT + r] = v.z;
        xs_T[(4 * c4 + 3) * XT + r] = v.w;
    }
    __syncthreads();

    const unsigned xtb = (unsigned)__cvta_generic_to_shared(xs_T) + lane * 8;
    const unsigned ub  = (unsigned)__cvta_generic_to_shared(U_s);
    const int H = wid & 3;

    float p0, p1;
    switch (wid >> 2) {
        case 0:  body<0>(xtb, ub, H, p0, p1); break;
        case 1:  body<1>(xtb, ub, H, p0, p1); break;
        case 2:  body<2>(xtb, ub, H, p0, p1); break;
        case 3:  body<3>(xtb, ub, H, p0, p1); break;
        case 4:  body<4>(xtb, ub, H, p0, p1); break;
        case 5:  body<5>(xtb, ub, H, p0, p1); break;
        case 6:  body<6>(xtb, ub, H, p0, p1); break;
        default: body<7>(xtb, ub, H, p0, p1); break;
    }

    // part[wid][2l..2l+1] via one 8B store (32 lanes -> 2 wf, no conflicts)
    {
        unsigned pa = (unsigned)__cvta_generic_to_shared(part)
                      + wid * 256 + lane * 8;
        asm volatile("st.shared.v2.f32 [%0], {%1,%2};" :: "r"(pa), "f"(p0), "f"(p1));
    }
    __syncthreads();

    // --- Warps 0-1 combine the 32 (C,H) partials per row
    if (wid < 2) {
        int r = (wid << 5) + lane;
        float s = part[0][r];
        #pragma unroll
        for (int c = 1; c < 32; ++c) s += part[c][r];
        out[row0 + r] = s + __ldg(bias);
    }
}

extern "C" void kernel_launch(void* const* d_in, const int* in_sizes, int n_in,
                              void* d_out, int out_size) {
    const float* x = (const float*)d_in[0];   // (16384, 64) f32
    const float* W = (const float*)d_in[1];   // (2145,)  f32 (first 2080 used)
    const float* b = (const float*)d_in[2];   // (1,)     f32
    float*     out = (float*)d_out;           // (16384,) f32

    const int blocks = out_size / 64;         // 256 CTAs x 1024 threads
    honu_kernel<<<blocks, THREADS>>>(x, W, b, out);
}